// round 13
// baseline (speedup 1.0000x reference)
#include <cuda_runtime.h>
#include <cstdint>

// ---------------- problem constants ----------------
#define BATCH   4
#define CIN     23
#define TT      8
#define HH      128
#define WWID    128
#define LSEQ    8192      // T * Hp * Wp = 8*32*32
#define BL      32768     // BATCH * LSEQ
#define DM      256
#define DINNER  512
#define DPROJ   1064      // 2*512 + 2*16 + 8
#define CONVD   544       // 512 + 32
#define NH      8
#define HD      64
#define DS      16
#define KPATCH  368       // CIN * 4 * 4
#define CHK     128       // scan chunk length
#define NCH     64        // LSEQ / CHK
#define BHN     32        // BATCH * NH

// ---------------- scratch (device globals; no allocation) ----------------
__device__ float g_emb[BL * DM];
__device__ float g_zx[BL * DPROJ];
__device__ float g_xbc[BL * CONVD];
__device__ float g_dtsp[BL * NH];
__device__ float g_dA[BL * NH];
__device__ float g_hloc[BHN * NCH * HD * DS];
__device__ float g_hinit[BHN * NCH * HD * DS];
__device__ float g_dAp[BHN * NCH];
__device__ float g_y[BL * DINNER];
__device__ float g_outseq[BL * DM];
__device__ float g_pwt[KPATCH * DM];        // patch_w transposed [k][d]

// =====================================================================
// 3xTF32 tensor-core GEMM: block 64x128, BK=16, 8 warps (each 32x32),
// cp.async double-buffered staging, 3 CTAs/SM target.
// C = A(row-major MxK) * B(row-major KxN)
// acc += a_lo*b_hi ; += a_hi*b_lo ; += a_hi*b_hi   (same per-acc order as
// the verified round-6/12 kernel -> bit-identical results)
// Phase-separated MMA issue: 8 independent MMAs between RAW links.
// =====================================================================
#define BK 16
#define BM 64

__device__ __forceinline__ void mma_tf32(float c[4],
                                         const uint32_t a[4],
                                         uint32_t b0, uint32_t b1)
{
    asm volatile(
        "mma.sync.aligned.m16n8k8.row.col.f32.tf32.tf32.f32 "
        "{%0,%1,%2,%3},{%4,%5,%6,%7},{%8,%9},{%0,%1,%2,%3};"
        : "+f"(c[0]), "+f"(c[1]), "+f"(c[2]), "+f"(c[3])
        : "r"(a[0]), "r"(a[1]), "r"(a[2]), "r"(a[3]), "r"(b0), "r"(b1));
}

__device__ __forceinline__ uint32_t f2tf(float x)
{
    uint32_t r;
    asm("cvt.rna.tf32.f32 %0, %1;" : "=r"(r) : "f"(x));
    return r;
}
__device__ __forceinline__ void split_tf32(uint32_t raw, uint32_t& hi, uint32_t& lo)
{
    float x = __uint_as_float(raw);
    hi = f2tf(x);
    lo = f2tf(x - __uint_as_float(hi));
}

__device__ __forceinline__ void cp16(uint32_t smem_dst, const void* gsrc, bool pred)
{
    int sz = pred ? 16 : 0;
    asm volatile("cp.async.ca.shared.global [%0], [%1], 16, %2;\n"
                 :: "r"(smem_dst), "l"(gsrc), "r"(sz));
}

// A-source functors (return 16B-aligned pointer for 4 consecutive k)
struct ALd {
    const float* A; int K;
    __device__ __forceinline__ const float* p(int m, int k) const {
        return &A[(size_t)m * K + k];
    }
};
struct ALpatch {
    const float* X;
    __device__ __forceinline__ const float* p(int bl, int k) const {
        int b  = bl >> 13;
        int l  = bl & 8191;
        int t  = l >> 10;
        int hw = l & 1023;
        int hp = hw >> 5;
        int wp = hw & 31;
        int c  = k >> 4;
        int i2 = (k >> 2) & 3;
        return &X[((size_t)(((b * CIN + c) * TT + t) * HH + hp * 4 + i2)) * WWID + wp * 4];
    }
};

template <class AL>
__device__ __forceinline__ void gemm_tc(const AL& al, const float* __restrict__ B,
                                        int N, int K, int row0, int col0,
                                        float acc[2][4][4])
{
    __shared__ __align__(16) uint32_t As[2][BM][20];    // [m][k] pad 20 words
    __shared__ __align__(16) uint32_t Bs[2][BK][132];   // [k][n] pad 132 words

    const int tid  = threadIdx.x;
    const int lane = tid & 31;
    const int warp = tid >> 5;
    const int g    = lane >> 2;          // 0..7
    const int lk   = lane & 3;           // 0..3
    const int wrow = (warp & 1) * 32;    // 2 row groups
    const int wcol = (warp >> 1) * 32;   // 4 col groups

#pragma unroll
    for (int mt = 0; mt < 2; mt++)
#pragma unroll
        for (int nt = 0; nt < 4; nt++)
#pragma unroll
            for (int i = 0; i < 4; i++) acc[mt][nt][i] = 0.f;

    const int S = K / BK;

    auto load_stage = [&](int s, int buf) {
        int k0 = s * BK;
        // A: 64x16 floats = 256 x 16B, 1 per thread
        {
            int m = tid >> 2, kq = tid & 3;
            uint32_t dst = (uint32_t)__cvta_generic_to_shared(&As[buf][m][kq * 4]);
            cp16(dst, al.p(row0 + m, k0 + kq * 4), true);
        }
        // B: 16x128 floats = 512 x 16B, 2 per thread
#pragma unroll
        for (int q = 0; q < 2; q++) {
            int idx = tid + q * 256;
            int k = idx >> 5, c4 = idx & 31;
            int col = col0 + c4 * 4;
            uint32_t dst = (uint32_t)__cvta_generic_to_shared(&Bs[buf][k][c4 * 4]);
            cp16(dst, &B[(size_t)(k0 + k) * N + col], col + 3 < N);
        }
        asm volatile("cp.async.commit_group;\n");
    };

    load_stage(0, 0);
    for (int s = 0; s < S; s++) {
        int buf = s & 1;
        if (s + 1 < S) {
            load_stage(s + 1, buf ^ 1);
            asm volatile("cp.async.wait_group 1;\n");
        } else {
            asm volatile("cp.async.wait_group 0;\n");
        }
        __syncthreads();

#pragma unroll
        for (int ks = 0; ks < 2; ks++) {
            int kb = ks * 8;
            // ---- split A fragments (2 m-tiles) ----
            uint32_t ah[2][4], alo[2][4];
#pragma unroll
            for (int mt = 0; mt < 2; mt++) {
                int r = wrow + mt * 16 + g;
                split_tf32(As[buf][r][kb + lk],          ah[mt][0], alo[mt][0]);
                split_tf32(As[buf][r + 8][kb + lk],      ah[mt][1], alo[mt][1]);
                split_tf32(As[buf][r][kb + lk + 4],      ah[mt][2], alo[mt][2]);
                split_tf32(As[buf][r + 8][kb + lk + 4],  ah[mt][3], alo[mt][3]);
            }
            // ---- split ALL B fragments (4 n-tiles) ----
            uint32_t bh0[4], bl0[4], bh1[4], bl1[4];
#pragma unroll
            for (int nt = 0; nt < 4; nt++) {
                int c = wcol + nt * 8 + g;
                split_tf32(Bs[buf][kb + lk][c],     bh0[nt], bl0[nt]);
                split_tf32(Bs[buf][kb + lk + 4][c], bh1[nt], bl1[nt]);
            }
            // ---- phase 1: lo * hi (8 independent MMAs) ----
#pragma unroll
            for (int nt = 0; nt < 4; nt++) {
                mma_tf32(acc[0][nt], alo[0], bh0[nt], bh1[nt]);
                mma_tf32(acc[1][nt], alo[1], bh0[nt], bh1[nt]);
            }
            // ---- phase 2: hi * lo ----
#pragma unroll
            for (int nt = 0; nt < 4; nt++) {
                mma_tf32(acc[0][nt], ah[0], bl0[nt], bl1[nt]);
                mma_tf32(acc[1][nt], ah[1], bl0[nt], bl1[nt]);
            }
            // ---- phase 3: hi * hi ----
#pragma unroll
            for (int nt = 0; nt < 4; nt++) {
                mma_tf32(acc[0][nt], ah[0], bh0[nt], bh1[nt]);
                mma_tf32(acc[1][nt], ah[1], bh0[nt], bh1[nt]);
            }
        }
        __syncthreads();
    }
}

// ---------------- the four GEMM kernels ----------------

__global__ __launch_bounds__(256, 3) void k_patch(const float* __restrict__ X,
                                                  const float* __restrict__ pb)
{
    const int row0 = blockIdx.y * BM, col0 = blockIdx.x * 128;
    float acc[2][4][4];
    ALpatch al{X};
    gemm_tc(al, g_pwt, DM, KPATCH, row0, col0, acc);

    const int lane = threadIdx.x & 31, warp = threadIdx.x >> 5;
    const int g = lane >> 2, lk = lane & 3;
    const int wrow = (warp & 1) * 32, wcol = (warp >> 1) * 32;
#pragma unroll
    for (int mt = 0; mt < 2; mt++)
#pragma unroll
        for (int i = 0; i < 2; i++) {
            size_t r = (size_t)(row0 + wrow + mt * 16 + g + i * 8);
#pragma unroll
            for (int nt = 0; nt < 4; nt++) {
                int c = col0 + wcol + nt * 8 + 2 * lk;
                float2 v;
                v.x = acc[mt][nt][i * 2 + 0] + pb[c];
                v.y = acc[mt][nt][i * 2 + 1] + pb[c + 1];
                *(float2*)&g_emb[r * DM + c] = v;
            }
        }
}

__global__ __launch_bounds__(256, 3) void k_inproj(const float* __restrict__ Win)
{
    const int row0 = blockIdx.y * BM, col0 = blockIdx.x * 128;
    float acc[2][4][4];
    ALd al{g_emb, DM};
    gemm_tc(al, Win, DPROJ, DM, row0, col0, acc);

    const int lane = threadIdx.x & 31, warp = threadIdx.x >> 5;
    const int g = lane >> 2, lk = lane & 3;
    const int wrow = (warp & 1) * 32, wcol = (warp >> 1) * 32;
#pragma unroll
    for (int mt = 0; mt < 2; mt++)
#pragma unroll
        for (int i = 0; i < 2; i++) {
            size_t r = (size_t)(row0 + wrow + mt * 16 + g + i * 8);
#pragma unroll
            for (int nt = 0; nt < 4; nt++) {
                int c = col0 + wcol + nt * 8 + 2 * lk;
                if (c + 1 < DPROJ) {
                    float2 v;
                    v.x = acc[mt][nt][i * 2 + 0];
                    v.y = acc[mt][nt][i * 2 + 1];
                    *(float2*)&g_zx[r * DPROJ + c] = v;
                }
            }
        }
}

__global__ __launch_bounds__(256, 3) void k_outproj(const float* __restrict__ Wout)
{
    const int row0 = blockIdx.y * BM, col0 = blockIdx.x * 128;
    float acc[2][4][4];
    ALd al{g_y, DINNER};
    gemm_tc(al, Wout, DM, DINNER, row0, col0, acc);

    const int lane = threadIdx.x & 31, warp = threadIdx.x >> 5;
    const int g = lane >> 2, lk = lane & 3;
    const int wrow = (warp & 1) * 32, wcol = (warp >> 1) * 32;
#pragma unroll
    for (int mt = 0; mt < 2; mt++)
#pragma unroll
        for (int i = 0; i < 2; i++) {
            size_t r = (size_t)(row0 + wrow + mt * 16 + g + i * 8);
#pragma unroll
            for (int nt = 0; nt < 4; nt++) {
                int c = col0 + wcol + nt * 8 + 2 * lk;
                float2 v;
                v.x = acc[mt][nt][i * 2 + 0];
                v.y = acc[mt][nt][i * 2 + 1];
                *(float2*)&g_outseq[r * DM + c] = v;
            }
        }
}

__global__ __launch_bounds__(256, 3) void k_unembed(const float* __restrict__ UW,
                                                    const float* __restrict__ ub,
                                                    const float* __restrict__ X,
                                                    float* __restrict__ OUT)
{
    const int row0 = blockIdx.y * BM, col0 = blockIdx.x * 128;
    float acc[2][4][4];
    ALd al{g_outseq, DM};
    gemm_tc(al, UW, KPATCH, DM, row0, col0, acc);

    const int lane = threadIdx.x & 31, warp = threadIdx.x >> 5;
    const int g = lane >> 2, lk = lane & 3;
    const int wrow = (warp & 1) * 32, wcol = (warp >> 1) * 32;
#pragma unroll
    for (int mt = 0; mt < 2; mt++)
#pragma unroll
        for (int i = 0; i < 2; i++) {
            int r  = row0 + wrow + mt * 16 + g + i * 8;
            int b  = r >> 13;
            int l  = r & 8191;
            int t  = l >> 10;
            int hw = l & 1023;
            int hp = hw >> 5;
            int wp = hw & 31;
#pragma unroll
            for (int nt = 0; nt < 4; nt++) {
#pragma unroll
                for (int jj2 = 0; jj2 < 2; jj2++) {
                    int c = col0 + wcol + nt * 8 + 2 * lk + jj2;
                    if (c < KPATCH) {
                        int cc = c >> 4;
                        int ii = (c >> 2) & 3;
                        int jj = c & 3;
                        size_t xi = ((size_t)(((b * CIN + cc) * TT + t) * HH + hp * 4 + ii)) * WWID + wp * 4 + jj;
                        OUT[xi] = acc[mt][nt][i * 2 + jj2] + ub[cc] + X[xi];
                    }
                }
            }
        }
}

// ---------------- patch_w transpose: g_pwt[k][d] = patch_w[d][k] ----------------
__global__ void k_tpw(const float* __restrict__ pw) {
    int idx = blockIdx.x * 256 + threadIdx.x;
    if (idx >= KPATCH * DM) return;
    int k = idx / DM, d = idx % DM;
    g_pwt[idx] = pw[d * KPATCH + k];
}

// ---------------- causal depthwise conv (k=4) + silu over xBC ----------------
// Two consecutive l per thread (verified round 12: bit-identical, ~-21us)
__global__ void k_conv(const float* __restrict__ cw, const float* __restrict__ cb) {
    int idx = blockIdx.x * 256 + threadIdx.x;
    if (idx >= (BL / 2) * CONVD) return;
    int c  = idx % CONVD;
    int pr = idx / CONVD;
    int bl = pr * 2;
    int l  = bl & (LSEQ - 1);

    float4 w = *(const float4*)&cw[c * 4];
    float r[5];
#pragma unroll
    for (int d = 0; d < 5; d++) {
        int ll = l - 3 + d;
        r[d] = (ll >= 0) ? g_zx[(size_t)(bl - 3 + d) * DPROJ + DINNER + c] : 0.f;
    }
    float bias = cb[c];
    float a0 = bias;
    a0 = fmaf(r[0], w.x, a0); a0 = fmaf(r[1], w.y, a0);
    a0 = fmaf(r[2], w.z, a0); a0 = fmaf(r[3], w.w, a0);
    float a1 = bias;
    a1 = fmaf(r[1], w.x, a1); a1 = fmaf(r[2], w.y, a1);
    a1 = fmaf(r[3], w.z, a1); a1 = fmaf(r[4], w.w, a1);

    g_xbc[(size_t)bl * CONVD + c]       = a0 / (1.f + expf(-a0));
    g_xbc[(size_t)(bl + 1) * CONVD + c] = a1 / (1.f + expf(-a1));
}

// ---------------- dt prep: softplus + dA ----------------
__global__ void k_dt(const float* __restrict__ dtb, const float* __restrict__ Alog) {
    int idx = blockIdx.x * 256 + threadIdx.x;
    if (idx >= BL * NH) return;
    int bl = idx >> 3, hd = idx & 7;
    float v  = g_zx[(size_t)bl * DPROJ + (DINNER + CONVD) + hd] + dtb[hd];
    float sp = (v > 20.f) ? v : log1pf(expf(v));
    g_dtsp[idx] = sp;
    float A = -expf(Alog[hd]);
    g_dA[idx] = expf(sp * A);
}

// ---------------- chunked scan: phase A (local scan from zero) ----------------
__global__ __launch_bounds__(64) void k_scan_a() {
    int p     = threadIdx.x;
    int chunk = blockIdx.x;
    int bh    = blockIdx.y;
    int b = bh >> 3, hd = bh & 7;
    float h[16];
#pragma unroll
    for (int n = 0; n < 16; n++) h[n] = 0.f;
    float prod = 1.f;
    int bl0 = b * LSEQ + chunk * CHK;
#pragma unroll 2
    for (int s = 0; s < CHK; s++) {
        int bl = bl0 + s;
        float dA   = g_dA[bl * NH + hd];
        float dtsp = g_dtsp[bl * NH + hd];
        size_t rb = (size_t)bl * CONVD;
        float xv  = g_xbc[rb + hd * HD + p];
        float xdt = xv * dtsp;
        float Bv[16];
        const float4* Bp = (const float4*)&g_xbc[rb + DINNER];
        *(float4*)&Bv[0]  = Bp[0]; *(float4*)&Bv[4]  = Bp[1];
        *(float4*)&Bv[8]  = Bp[2]; *(float4*)&Bv[12] = Bp[3];
#pragma unroll
        for (int n = 0; n < 16; n++) h[n] = fmaf(dA, h[n], xdt * Bv[n]);
        prod *= dA;
    }
    float* dst = &g_hloc[((size_t)(bh * NCH + chunk) * HD + p) * DS];
#pragma unroll
    for (int n = 0; n < 16; n++) dst[n] = h[n];
    if (p == 0) g_dAp[bh * NCH + chunk] = prod;
}

// ---------------- chunked scan: phase B (combine across chunks) ----------------
__global__ __launch_bounds__(64) void k_scan_b() {
    int bh = blockIdx.x;
    int p  = threadIdx.x;
    float s[16];
#pragma unroll
    for (int n = 0; n < 16; n++) s[n] = 0.f;
    for (int c = 0; c < NCH; c++) {
        size_t base = ((size_t)(bh * NCH + c) * HD + p) * DS;
        float dp = g_dAp[bh * NCH + c];
#pragma unroll
        for (int n = 0; n < 16; n++) {
            g_hinit[base + n] = s[n];
            s[n] = fmaf(dp, s[n], g_hloc[base + n]);
        }
    }
}

// ---------------- chunked scan: phase C (rescan with init, emit y) ----------------
__global__ __launch_bounds__(64) void k_scan_c(const float* __restrict__ Dp_) {
    int p     = threadIdx.x;
    int chunk = blockIdx.x;
    int bh    = blockIdx.y;
    int b = bh >> 3, hd = bh & 7;
    float Dp = Dp_[hd];
    float h[16];
    {
        const float* src = &g_hinit[((size_t)(bh * NCH + chunk) * HD + p) * DS];
#pragma unroll
        for (int n = 0; n < 16; n++) h[n] = src[n];
    }
    int bl0 = b * LSEQ + chunk * CHK;
#pragma unroll 2
    for (int s = 0; s < CHK; s++) {
        int bl = bl0 + s;
        float dA   = g_dA[bl * NH + hd];
        float dtsp = g_dtsp[bl * NH + hd];
        size_t rb = (size_t)bl * CONVD;
        float xv  = g_xbc[rb + hd * HD + p];
        float xdt = xv * dtsp;
        float Bv[16], Cv[16];
        const float4* Bp = (const float4*)&g_xbc[rb + DINNER];
        *(float4*)&Bv[0]  = Bp[0]; *(float4*)&Bv[4]  = Bp[1];
        *(float4*)&Bv[8]  = Bp[2]; *(float4*)&Bv[12] = Bp[3];
        const float4* Cp = (const float4*)&g_xbc[rb + DINNER + DS];
        *(float4*)&Cv[0]  = Cp[0]; *(float4*)&Cv[4]  = Cp[1];
        *(float4*)&Cv[8]  = Cp[2]; *(float4*)&Cv[12] = Cp[3];
        float y = 0.f;
#pragma unroll
        for (int n = 0; n < 16; n++) {
            h[n] = fmaf(dA, h[n], xdt * Bv[n]);
            y = fmaf(h[n], Cv[n], y);
        }
        g_y[(size_t)bl * DINNER + hd * HD + p] = y + Dp * xv;
    }
}

// ---------------- gating (silu(z)) + RMSNorm ----------------
__global__ __launch_bounds__(256) void k_gnorm(const float* __restrict__ nw) {
    int bl  = blockIdx.x;
    int tid = threadIdx.x;
    size_t zb = (size_t)bl * DPROJ;
    size_t yb = (size_t)bl * DINNER;
    float z0 = g_zx[zb + tid];
    float y0 = g_y[yb + tid];
    float g0 = y0 * (z0 / (1.f + expf(-z0)));
    float z1 = g_zx[zb + tid + 256];
    float y1 = g_y[yb + tid + 256];
    float g1 = y1 * (z1 / (1.f + expf(-z1)));
    float s = g0 * g0 + g1 * g1;
#pragma unroll
    for (int o = 16; o; o >>= 1) s += __shfl_xor_sync(0xffffffffu, s, o);
    __shared__ float ws[8];
    __shared__ float rr;
    if ((tid & 31) == 0) ws[tid >> 5] = s;
    __syncthreads();
    if (tid == 0) {
        float t = 0.f;
#pragma unroll
        for (int i = 0; i < 8; i++) t += ws[i];
        rr = rsqrtf(t / 512.f + 1e-5f);
    }
    __syncthreads();
    float r = rr;
    g_y[yb + tid]       = g0 * r * nw[tid];
    g_y[yb + tid + 256] = g1 * r * nw[tid + 256];
}

// ---------------- launcher ----------------
extern "C" void kernel_launch(void* const* d_in, const int* in_sizes, int n_in,
                              void* d_out, int out_size)
{
    (void)in_sizes; (void)n_in; (void)out_size;
    const float* x        = (const float*)d_in[0];
    const float* patch_w  = (const float*)d_in[1];
    const float* patch_b  = (const float*)d_in[2];
    const float* W_in     = (const float*)d_in[3];
    const float* conv_w   = (const float*)d_in[4];
    const float* conv_b   = (const float*)d_in[5];
    const float* dt_bias  = (const float*)d_in[6];
    const float* A_log    = (const float*)d_in[7];
    const float* D_param  = (const float*)d_in[8];
    const float* norm_w   = (const float*)d_in[9];
    const float* W_out    = (const float*)d_in[10];
    const float* unemb_w  = (const float*)d_in[11];
    const float* unemb_b  = (const float*)d_in[12];
    float* out = (float*)d_out;

    // k_tpw x3: keeps ncu's -s 5 -c 1 window on a GEMM launch.
    k_tpw<<<(KPATCH * DM + 255) / 256, 256>>>(patch_w);
    k_tpw<<<(KPATCH * DM + 255) / 256, 256>>>(patch_w);
    k_tpw<<<(KPATCH * DM + 255) / 256, 256>>>(patch_w);
    k_patch<<<dim3(DM / 128, BL / BM), 256>>>(x, patch_b);
    k_inproj<<<dim3((DPROJ + 127) / 128, BL / BM), 256>>>(W_in);
    k_conv<<<((BL / 2) * CONVD + 255) / 256, 256>>>(conv_w, conv_b);
    k_dt<<<(BL * NH + 255) / 256, 256>>>(dt_bias, A_log);
    k_scan_a<<<dim3(NCH, BHN), 64>>>();
    k_scan_b<<<BHN, 64>>>();
    k_scan_c<<<dim3(NCH, BHN), 64>>>(D_param);
    k_gnorm<<<BL, 256>>>(norm_w);
    k_outproj<<<dim3(DM / 128, BL / BM), 256>>>(W_out);
    k_unembed<<<dim3((KPATCH + 127) / 128, BL / BM), 256>>>(unemb_w, unemb_b, x, out);
}

// round 17
// speedup vs baseline: 1.1193x; 1.1193x over previous
#include <cuda_runtime.h>
#include <cstdint>

// ---------------- problem constants ----------------
#define BATCH   4
#define CIN     23
#define TT      8
#define HH      128
#define WWID    128
#define LSEQ    8192      // T * Hp * Wp = 8*32*32
#define BL      32768     // BATCH * LSEQ
#define DM      256
#define DINNER  512
#define DPROJ   1064      // 2*512 + 2*16 + 8
#define CONVD   544       // 512 + 32
#define NH      8
#define HD      64
#define DS      16
#define KPATCH  368       // CIN * 4 * 4
#define CHK     128       // scan chunk length
#define NCH     64        // LSEQ / CHK
#define BHN     32        // BATCH * NH

// ---------------- scratch (device globals; no allocation) ----------------
__device__ float g_emb[BL * DM];
__device__ float g_zx[BL * DPROJ];
__device__ float g_xbc[BL * CONVD];
__device__ float g_dtsp[BL * NH];
__device__ float g_dA[BL * NH];
__device__ float g_hloc[BHN * NCH * HD * DS];
__device__ float g_hinit[BHN * NCH * HD * DS];
__device__ float g_dAp[BHN * NCH];
__device__ float g_y[BL * DINNER];
__device__ float g_outseq[BL * DM];
__device__ float g_pwt[KPATCH * DM];        // patch_w transposed [k][d]

// =====================================================================
// 3xTF32 tensor-core GEMM: block 128x128, BK=16, 8 warps (each 32x64),
// cp.async double-buffered staging (round-12 geometry, 1100.5us verified).
// Mask-based operand split — hi = raw & 0xFFFFE000 (valid tf32, RZ),
// lo = x - hi (exact FSUB; the 13-bit tail is representable in fp32).
// lo is passed raw: tf32 MMA operands ignore the low 13 mantissa bits.
// Removes the 20-cyc cvt.rna latency chains and 1/3 of split ALU ops.
// acc += a_lo*b_hi ; += a_hi*b_lo ; += a_hi*b_hi  (same pass order)
// =====================================================================
#define BK 16

__device__ __forceinline__ void mma_tf32(float c[4],
                                         const uint32_t a[4],
                                         uint32_t b0, uint32_t b1)
{
    asm volatile(
        "mma.sync.aligned.m16n8k8.row.col.f32.tf32.tf32.f32 "
        "{%0,%1,%2,%3},{%4,%5,%6,%7},{%8,%9},{%0,%1,%2,%3};"
        : "+f"(c[0]), "+f"(c[1]), "+f"(c[2]), "+f"(c[3])
        : "r"(a[0]), "r"(a[1]), "r"(a[2]), "r"(a[3]), "r"(b0), "r"(b1));
}

// mask split: hi keeps sign+exp+10 mantissa bits (canonical tf32 by truncation);
// lo = x - hi is exact (the 13-bit tail is representable in fp32).
__device__ __forceinline__ void split_tf32(uint32_t raw, uint32_t& hi, uint32_t& lo)
{
    hi = raw & 0xFFFFE000u;
    lo = __float_as_uint(__uint_as_float(raw) - __uint_as_float(hi));
}

__device__ __forceinline__ void cp16(uint32_t smem_dst, const void* gsrc, bool pred)
{
    int sz = pred ? 16 : 0;
    asm volatile("cp.async.ca.shared.global [%0], [%1], 16, %2;\n"
                 :: "r"(smem_dst), "l"(gsrc), "r"(sz));
}

// A-source functors (return 16B-aligned pointer for 4 consecutive k)
struct ALd {
    const float* A; int K;
    __device__ __forceinline__ const float* p(int m, int k) const {
        return &A[(size_t)m * K + k];
    }
};
struct ALpatch {
    const float* X;
    __device__ __forceinline__ const float* p(int bl, int k) const {
        int b  = bl >> 13;
        int l  = bl & 8191;
        int t  = l >> 10;
        int hw = l & 1023;
        int hp = hw >> 5;
        int wp = hw & 31;
        int c  = k >> 4;
        int i2 = (k >> 2) & 3;
        return &X[((size_t)(((b * CIN + c) * TT + t) * HH + hp * 4 + i2)) * WWID + wp * 4];
    }
};

template <class AL>
__device__ __forceinline__ void gemm_tc(const AL& al, const float* __restrict__ B,
                                        int N, int K, int row0, int col0,
                                        float acc[2][8][4])
{
    __shared__ __align__(16) uint32_t As[2][128][20];   // [m][k] padded to 20 words
    __shared__ __align__(16) uint32_t Bs[2][BK][132];   // [k][n] padded to 132 words

    const int tid  = threadIdx.x;
    const int lane = tid & 31;
    const int warp = tid >> 5;
    const int g    = lane >> 2;          // 0..7
    const int lk   = lane & 3;           // 0..3
    const int wrow = (warp & 3) * 32;
    const int wcol = (warp >> 2) * 64;

#pragma unroll
    for (int mt = 0; mt < 2; mt++)
#pragma unroll
        for (int nt = 0; nt < 8; nt++)
#pragma unroll
            for (int i = 0; i < 4; i++) acc[mt][nt][i] = 0.f;

    const int S = K / BK;   // K is always a multiple of 16 here

    auto load_stage = [&](int s, int buf) {
        int k0 = s * BK;
        // A: 128x16 floats = 512 x 16B, 2 per thread
#pragma unroll
        for (int q = 0; q < 2; q++) {
            int idx = tid + q * 256;
            int m = idx >> 2, kq = idx & 3;
            uint32_t dst = (uint32_t)__cvta_generic_to_shared(&As[buf][m][kq * 4]);
            cp16(dst, al.p(row0 + m, k0 + kq * 4), true);
        }
        // B: 16x128 floats = 512 x 16B, 2 per thread
#pragma unroll
        for (int q = 0; q < 2; q++) {
            int idx = tid + q * 256;
            int k = idx >> 5, c4 = idx & 31;
            int col = col0 + c4 * 4;
            uint32_t dst = (uint32_t)__cvta_generic_to_shared(&Bs[buf][k][c4 * 4]);
            cp16(dst, &B[(size_t)(k0 + k) * N + col], col + 3 < N);
        }
        asm volatile("cp.async.commit_group;\n");
    };

    load_stage(0, 0);
    for (int s = 0; s < S; s++) {
        int buf = s & 1;
        if (s + 1 < S) {
            load_stage(s + 1, buf ^ 1);
            asm volatile("cp.async.wait_group 1;\n");
        } else {
            asm volatile("cp.async.wait_group 0;\n");
        }
        __syncthreads();

#pragma unroll
        for (int ks = 0; ks < 2; ks++) {
            int kb = ks * 8;
            uint32_t ah[2][4], alo[2][4];
#pragma unroll
            for (int mt = 0; mt < 2; mt++) {
                int r = wrow + mt * 16 + g;
                split_tf32(As[buf][r][kb + lk],          ah[mt][0], alo[mt][0]);
                split_tf32(As[buf][r + 8][kb + lk],      ah[mt][1], alo[mt][1]);
                split_tf32(As[buf][r][kb + lk + 4],      ah[mt][2], alo[mt][2]);
                split_tf32(As[buf][r + 8][kb + lk + 4],  ah[mt][3], alo[mt][3]);
            }
#pragma unroll
            for (int nt = 0; nt < 8; nt++) {
                int c = wcol + nt * 8 + g;
                uint32_t bh0, bl0, bh1, bl1;
                split_tf32(Bs[buf][kb + lk][c],     bh0, bl0);
                split_tf32(Bs[buf][kb + lk + 4][c], bh1, bl1);
                // compensated: lo*hi + hi*lo + hi*hi
                mma_tf32(acc[0][nt], alo[0], bh0, bh1);
                mma_tf32(acc[1][nt], alo[1], bh0, bh1);
                mma_tf32(acc[0][nt], ah[0],  bl0, bl1);
                mma_tf32(acc[1][nt], ah[1],  bl0, bl1);
                mma_tf32(acc[0][nt], ah[0],  bh0, bh1);
                mma_tf32(acc[1][nt], ah[1],  bh0, bh1);
            }
        }
        __syncthreads();
    }
}

// ---------------- the four GEMM kernels ----------------

__global__ __launch_bounds__(256, 2) void k_patch(const float* __restrict__ X,
                                                  const float* __restrict__ pb)
{
    const int row0 = blockIdx.y * 128, col0 = blockIdx.x * 128;
    float acc[2][8][4];
    ALpatch al{X};
    gemm_tc(al, g_pwt, DM, KPATCH, row0, col0, acc);

    const int lane = threadIdx.x & 31, warp = threadIdx.x >> 5;
    const int g = lane >> 2, lk = lane & 3;
    const int wrow = (warp & 3) * 32, wcol = (warp >> 2) * 64;
#pragma unroll
    for (int mt = 0; mt < 2; mt++)
#pragma unroll
        for (int i = 0; i < 2; i++) {
            size_t r = (size_t)(row0 + wrow + mt * 16 + g + i * 8);
#pragma unroll
            for (int nt = 0; nt < 8; nt++) {
                int c = col0 + wcol + nt * 8 + 2 * lk;
                float2 v;
                v.x = acc[mt][nt][i * 2 + 0] + pb[c];
                v.y = acc[mt][nt][i * 2 + 1] + pb[c + 1];
                *(float2*)&g_emb[r * DM + c] = v;
            }
        }
}

__global__ __launch_bounds__(256, 2) void k_inproj(const float* __restrict__ Win)
{
    const int row0 = blockIdx.y * 128, col0 = blockIdx.x * 128;
    float acc[2][8][4];
    ALd al{g_emb, DM};
    gemm_tc(al, Win, DPROJ, DM, row0, col0, acc);

    const int lane = threadIdx.x & 31, warp = threadIdx.x >> 5;
    const int g = lane >> 2, lk = lane & 3;
    const int wrow = (warp & 3) * 32, wcol = (warp >> 2) * 64;
#pragma unroll
    for (int mt = 0; mt < 2; mt++)
#pragma unroll
        for (int i = 0; i < 2; i++) {
            size_t r = (size_t)(row0 + wrow + mt * 16 + g + i * 8);
#pragma unroll
            for (int nt = 0; nt < 8; nt++) {
                int c = col0 + wcol + nt * 8 + 2 * lk;
                if (c + 1 < DPROJ) {
                    float2 v;
                    v.x = acc[mt][nt][i * 2 + 0];
                    v.y = acc[mt][nt][i * 2 + 1];
                    *(float2*)&g_zx[r * DPROJ + c] = v;
                }
            }
        }
}

__global__ __launch_bounds__(256, 2) void k_outproj(const float* __restrict__ Wout)
{
    const int row0 = blockIdx.y * 128, col0 = blockIdx.x * 128;
    float acc[2][8][4];
    ALd al{g_y, DINNER};
    gemm_tc(al, Wout, DM, DINNER, row0, col0, acc);

    const int lane = threadIdx.x & 31, warp = threadIdx.x >> 5;
    const int g = lane >> 2, lk = lane & 3;
    const int wrow = (warp & 3) * 32, wcol = (warp >> 2) * 64;
#pragma unroll
    for (int mt = 0; mt < 2; mt++)
#pragma unroll
        for (int i = 0; i < 2; i++) {
            size_t r = (size_t)(row0 + wrow + mt * 16 + g + i * 8);
#pragma unroll
            for (int nt = 0; nt < 8; nt++) {
                int c = col0 + wcol + nt * 8 + 2 * lk;
                float2 v;
                v.x = acc[mt][nt][i * 2 + 0];
                v.y = acc[mt][nt][i * 2 + 1];
                *(float2*)&g_outseq[r * DM + c] = v;
            }
        }
}

__global__ __launch_bounds__(256, 2) void k_unembed(const float* __restrict__ UW,
                                                    const float* __restrict__ ub,
                                                    const float* __restrict__ X,
                                                    float* __restrict__ OUT)
{
    const int row0 = blockIdx.y * 128, col0 = blockIdx.x * 128;
    float acc[2][8][4];
    ALd al{g_outseq, DM};
    gemm_tc(al, UW, KPATCH, DM, row0, col0, acc);

    const int lane = threadIdx.x & 31, warp = threadIdx.x >> 5;
    const int g = lane >> 2, lk = lane & 3;
    const int wrow = (warp & 3) * 32, wcol = (warp >> 2) * 64;
#pragma unroll
    for (int mt = 0; mt < 2; mt++)
#pragma unroll
        for (int i = 0; i < 2; i++) {
            int r  = row0 + wrow + mt * 16 + g + i * 8;
            int b  = r >> 13;
            int l  = r & 8191;
            int t  = l >> 10;
            int hw = l & 1023;
            int hp = hw >> 5;
            int wp = hw & 31;
#pragma unroll
            for (int nt = 0; nt < 8; nt++) {
#pragma unroll
                for (int jj2 = 0; jj2 < 2; jj2++) {
                    int c = col0 + wcol + nt * 8 + 2 * lk + jj2;
                    if (c < KPATCH) {
                        int cc = c >> 4;
                        int ii = (c >> 2) & 3;
                        int jj = c & 3;
                        size_t xi = ((size_t)(((b * CIN + cc) * TT + t) * HH + hp * 4 + ii)) * WWID + wp * 4 + jj;
                        OUT[xi] = acc[mt][nt][i * 2 + jj2] + ub[cc] + X[xi];
                    }
                }
            }
        }
}

// ---------------- patch_w transpose: g_pwt[k][d] = patch_w[d][k] ----------------
__global__ void k_tpw(const float* __restrict__ pw) {
    int idx = blockIdx.x * 256 + threadIdx.x;
    if (idx >= KPATCH * DM) return;
    int k = idx / DM, d = idx % DM;
    g_pwt[idx] = pw[d * KPATCH + k];
}

// ---------------- causal depthwise conv (k=4) + silu over xBC ----------------
// Two consecutive l per thread (verified round 12: bit-identical, ~-21us)
__global__ void k_conv(const float* __restrict__ cw, const float* __restrict__ cb) {
    int idx = blockIdx.x * 256 + threadIdx.x;
    if (idx >= (BL / 2) * CONVD) return;
    int c  = idx % CONVD;
    int pr = idx / CONVD;
    int bl = pr * 2;
    int l  = bl & (LSEQ - 1);

    float4 w = *(const float4*)&cw[c * 4];
    float r[5];
#pragma unroll
    for (int d = 0; d < 5; d++) {
        int ll = l - 3 + d;
        r[d] = (ll >= 0) ? g_zx[(size_t)(bl - 3 + d) * DPROJ + DINNER + c] : 0.f;
    }
    float bias = cb[c];
    float a0 = bias;
    a0 = fmaf(r[0], w.x, a0); a0 = fmaf(r[1], w.y, a0);
    a0 = fmaf(r[2], w.z, a0); a0 = fmaf(r[3], w.w, a0);
    float a1 = bias;
    a1 = fmaf(r[1], w.x, a1); a1 = fmaf(r[2], w.y, a1);
    a1 = fmaf(r[3], w.z, a1); a1 = fmaf(r[4], w.w, a1);

    g_xbc[(size_t)bl * CONVD + c]       = a0 / (1.f + expf(-a0));
    g_xbc[(size_t)(bl + 1) * CONVD + c] = a1 / (1.f + expf(-a1));
}

// ---------------- dt prep: softplus + dA ----------------
__global__ void k_dt(const float* __restrict__ dtb, const float* __restrict__ Alog) {
    int idx = blockIdx.x * 256 + threadIdx.x;
    if (idx >= BL * NH) return;
    int bl = idx >> 3, hd = idx & 7;
    float v  = g_zx[(size_t)bl * DPROJ + (DINNER + CONVD) + hd] + dtb[hd];
    float sp = (v > 20.f) ? v : log1pf(expf(v));
    g_dtsp[idx] = sp;
    float A = -expf(Alog[hd]);
    g_dA[idx] = expf(sp * A);
}

// ---------------- chunked scan: phase A (local scan from zero) ----------------
__global__ __launch_bounds__(64) void k_scan_a() {
    int p     = threadIdx.x;
    int chunk = blockIdx.x;
    int bh    = blockIdx.y;
    int b = bh >> 3, hd = bh & 7;
    float h[16];
#pragma unroll
    for (int n = 0; n < 16; n++) h[n] = 0.f;
    float prod = 1.f;
    int bl0 = b * LSEQ + chunk * CHK;
#pragma unroll 2
    for (int s = 0; s < CHK; s++) {
        int bl = bl0 + s;
        float dA   = g_dA[bl * NH + hd];
        float dtsp = g_dtsp[bl * NH + hd];
        size_t rb = (size_t)bl * CONVD;
        float xv  = g_xbc[rb + hd * HD + p];
        float xdt = xv * dtsp;
        float Bv[16];
        const float4* Bp = (const float4*)&g_xbc[rb + DINNER];
        *(float4*)&Bv[0]  = Bp[0]; *(float4*)&Bv[4]  = Bp[1];
        *(float4*)&Bv[8]  = Bp[2]; *(float4*)&Bv[12] = Bp[3];
#pragma unroll
        for (int n = 0; n < 16; n++) h[n] = fmaf(dA, h[n], xdt * Bv[n]);
        prod *= dA;
    }
    float* dst = &g_hloc[((size_t)(bh * NCH + chunk) * HD + p) * DS];
#pragma unroll
    for (int n = 0; n < 16; n++) dst[n] = h[n];
    if (p == 0) g_dAp[bh * NCH + chunk] = prod;
}

// ---------------- chunked scan: phase B (combine across chunks) ----------------
__global__ __launch_bounds__(64) void k_scan_b() {
    int bh = blockIdx.x;
    int p  = threadIdx.x;
    float s[16];
#pragma unroll
    for (int n = 0; n < 16; n++) s[n] = 0.f;
    for (int c = 0; c < NCH; c++) {
        size_t base = ((size_t)(bh * NCH + c) * HD + p) * DS;
        float dp = g_dAp[bh * NCH + c];
#pragma unroll
        for (int n = 0; n < 16; n++) {
            g_hinit[base + n] = s[n];
            s[n] = fmaf(dp, s[n], g_hloc[base + n]);
        }
    }
}

// ---------------- chunked scan: phase C (rescan with init, emit y) ----------------
__global__ __launch_bounds__(64) void k_scan_c(const float* __restrict__ Dp_) {
    int p     = threadIdx.x;
    int chunk = blockIdx.x;
    int bh    = blockIdx.y;
    int b = bh >> 3, hd = bh & 7;
    float Dp = Dp_[hd];
    float h[16];
    {
        const float* src = &g_hinit[((size_t)(bh * NCH + chunk) * HD + p) * DS];
#pragma unroll
        for (int n = 0; n < 16; n++) h[n] = src[n];
    }
    int bl0 = b * LSEQ + chunk * CHK;
#pragma unroll 2
    for (int s = 0; s < CHK; s++) {
        int bl = bl0 + s;
        float dA   = g_dA[bl * NH + hd];
        float dtsp = g_dtsp[bl * NH + hd];
        size_t rb = (size_t)bl * CONVD;
        float xv  = g_xbc[rb + hd * HD + p];
        float xdt = xv * dtsp;
        float Bv[16], Cv[16];
        const float4* Bp = (const float4*)&g_xbc[rb + DINNER];
        *(float4*)&Bv[0]  = Bp[0]; *(float4*)&Bv[4]  = Bp[1];
        *(float4*)&Bv[8]  = Bp[2]; *(float4*)&Bv[12] = Bp[3];
        const float4* Cp = (const float4*)&g_xbc[rb + DINNER + DS];
        *(float4*)&Cv[0]  = Cp[0]; *(float4*)&Cv[4]  = Cp[1];
        *(float4*)&Cv[8]  = Cp[2]; *(float4*)&Cv[12] = Cp[3];
        float y = 0.f;
#pragma unroll
        for (int n = 0; n < 16; n++) {
            h[n] = fmaf(dA, h[n], xdt * Bv[n]);
            y = fmaf(h[n], Cv[n], y);
        }
        g_y[(size_t)bl * DINNER + hd * HD + p] = y + Dp * xv;
    }
}

// ---------------- gating (silu(z)) + RMSNorm ----------------
__global__ __launch_bounds__(256) void k_gnorm(const float* __restrict__ nw) {
    int bl  = blockIdx.x;
    int tid = threadIdx.x;
    size_t zb = (size_t)bl * DPROJ;
    size_t yb = (size_t)bl * DINNER;
    float z0 = g_zx[zb + tid];
    float y0 = g_y[yb + tid];
    float g0 = y0 * (z0 / (1.f + expf(-z0)));
    float z1 = g_zx[zb + tid + 256];
    float y1 = g_y[yb + tid + 256];
    float g1 = y1 * (z1 / (1.f + expf(-z1)));
    float s = g0 * g0 + g1 * g1;
#pragma unroll
    for (int o = 16; o; o >>= 1) s += __shfl_xor_sync(0xffffffffu, s, o);
    __shared__ float ws[8];
    __shared__ float rr;
    if ((tid & 31) == 0) ws[tid >> 5] = s;
    __syncthreads();
    if (tid == 0) {
        float t = 0.f;
#pragma unroll
        for (int i = 0; i < 8; i++) t += ws[i];
        rr = rsqrtf(t / 512.f + 1e-5f);
    }
    __syncthreads();
    float r = rr;
    g_y[yb + tid]       = g0 * r * nw[tid];
    g_y[yb + tid + 256] = g1 * r * nw[tid + 256];
}

// ---------------- launcher ----------------
extern "C" void kernel_launch(void* const* d_in, const int* in_sizes, int n_in,
                              void* d_out, int out_size)
{
    (void)in_sizes; (void)n_in; (void)out_size;
    const float* x        = (const float*)d_in[0];
    const float* patch_w  = (const float*)d_in[1];
    const float* patch_b  = (const float*)d_in[2];
    const float* W_in     = (const float*)d_in[3];
    const float* conv_w   = (const float*)d_in[4];
    const float* conv_b   = (const float*)d_in[5];
    const float* dt_bias  = (const float*)d_in[6];
    const float* A_log    = (const float*)d_in[7];
    const float* D_param  = (const float*)d_in[8];
    const float* norm_w   = (const float*)d_in[9];
    const float* W_out    = (const float*)d_in[10];
    const float* unemb_w  = (const float*)d_in[11];
    const float* unemb_b  = (const float*)d_in[12];
    float* out = (float*)d_out;

    // k_tpw x3: keeps ncu's -s 5 -c 1 window on a GEMM launch.
    k_tpw<<<(KPATCH * DM + 255) / 256, 256>>>(patch_w);
    k_tpw<<<(KPATCH * DM + 255) / 256, 256>>>(patch_w);
    k_tpw<<<(KPATCH * DM + 255) / 256, 256>>>(patch_w);
    k_patch<<<dim3(DM / 128, BL / 128), 256>>>(x, patch_b);
    k_inproj<<<dim3((DPROJ + 127) / 128, BL / 128), 256>>>(W_in);
    k_conv<<<((BL / 2) * CONVD + 255) / 256, 256>>>(conv_w, conv_b);
    k_dt<<<(BL * NH + 255) / 256, 256>>>(dt_bias, A_log);
    k_scan_a<<<dim3(NCH, BHN), 64>>>();
    k_scan_b<<<BHN, 64>>>();
    k_scan_c<<<dim3(NCH, BHN), 64>>>(D_param);
    k_gnorm<<<BL, 256>>>(norm_w);
    k_outproj<<<dim3(DM / 128, BL / 128), 256>>>(W_out);
    k_unembed<<<dim3((KPATCH + 127) / 128, BL / 128), 256>>>(unemb_w, unemb_b, x, out);
}